// round 5
// baseline (speedup 1.0000x reference)
#include <cuda_runtime.h>
#include <math.h>

#define T_LEN  2000
#define FC     514            // 257 * 2
#define NSER   8224           // 16 * 514
#define NPAIRS (NSER / 2)     // 4112 float2 series-pairs
#define FC2    (FC / 2)       // 257 pairs per row
#define CH     80             // number of time chunks
#define LCH    25             // chunk length (CH*LCH == T_LEN)

// Per-t constants: (w, a = 1-w, b = w*a, bP = b * Ppre_u).
__device__ float4 g_c4[T_LEN];
// Per-chunk constants: (P, gamma).
__device__ float2 g_ck[CH];
// Per (chunk, series) scratch.
__device__ float g_q [CH * NSER];
__device__ float g_al[CH * NSER];
__device__ float g_be[CH * NSER];
__device__ float g_v2[CH * NSER];
__device__ float g_s [CH * NSER];

// Single block: phase 1 builds beta^t table (1 pow per thread slot),
// phase 2 derives every constant with cheap arithmetic.
__global__ __launch_bounds__(1024)
void coef_kernel() {
    __shared__ double sbt[T_LEN + 1];        // beta^t, t = 0..2000
    const double b  = (double)0.99f;
    const double c1 = (double)(1.0f - 0.99f);   // exact
    int tid = threadIdx.x;
    for (int t = tid; t <= T_LEN; t += 1024)
        sbt[t] = pow(b, (double)t);
    __syncthreads();

    for (int t = tid; t < T_LEN; t += 1024) {
        double w  = c1 / (1.0 - sbt[t + 1]); // w_0 == 1 exactly
        double a  = 1.0 - w;
        double bb = w * a;
        int u  = t % LCH;
        int t0 = t - u;
        // Ppre_u = beta^u (1-beta^t0)/(1-beta^t); Ppre_0 = 1 (t0 chunk-start).
        double Ppre = (u == 0) ? 1.0
                    : sbt[u] * (1.0 - sbt[t0]) / (1.0 - sbt[t]);
        g_c4[t] = make_float4((float)w, (float)a, (float)bb, (float)(bb * Ppre));
    }
    if (tid < CH) {
        int t0 = tid * LCH;
        double ratio = (1.0 - sbt[t0]) / (1.0 - sbt[t0 + LCH]);
        double P     = sbt[LCH] * ratio;     // 0 for chunk 0
        double ga    = (P / sbt[t0]) * (1.0 - ratio);
        g_ck[tid] = make_float2((float)P, (float)ga);
    }
}

// Pass 1: per (chunk, pair) compute (Q, alpha, beta-hat) from zero start.
__global__ __launch_bounds__(256)
void pass1_kernel(const float* __restrict__ in) {
    int pr = blockIdx.x * 256 + threadIdx.x;
    int c  = blockIdx.y;
    if (pr >= NPAIRS) return;
    int n  = pr / FC2;
    int fp = pr - n * FC2;
    const float2* xp = (const float2*)in
                     + ((size_t)n * T_LEN + (size_t)c * LCH) * FC2 + fp;
    const float4* cf = g_c4 + c * LCH;

    float Q0 = 0.f, Q1 = 0.f, al0 = 0.f, al1 = 0.f, be0 = 0.f, be1 = 0.f;
#pragma unroll
    for (int u = 0; u < LCH; u++) {
        float4 k = __ldg(cf + u);                // (w, a, b, bP)
        float2 x = __ldg(xp + (size_t)u * FC2);
        float u0 = x.x - Q0;
        float u1 = x.y - Q1;
        Q0 = fmaf(k.x, u0, Q0);
        Q1 = fmaf(k.x, u1, Q1);
        al0 = fmaf(k.y, al0, (k.z * u0) * u0);
        al1 = fmaf(k.y, al1, (k.z * u1) * u1);
        be0 = fmaf(k.y, be0, k.w * u0);
        be1 = fmaf(k.y, be1, k.w * u1);
    }
    int idx = c * NSER + pr * 2;
    *(float2*)&g_q [idx] = make_float2(Q0, Q1);
    *(float2*)&g_al[idx] = make_float2(al0, al1);
    *(float2*)&g_be[idx] = make_float2(be0, be1);
}

// Combine: serial over the chunks per series-pair.
__global__ __launch_bounds__(256)
void combine_kernel() {
    int pr = blockIdx.x * 256 + threadIdx.x;
    if (pr >= NPAIRS) return;
    float v20 = 0.f, v21 = 0.f, S0 = 0.f, S1 = 0.f;
#pragma unroll 8
    for (int c = 0; c < CH; c++) {
        int idx = c * NSER + pr * 2;
        float2 pg = __ldg(&g_ck[c]);             // (P, gamma)
        float2 q  = __ldg((const float2*)&g_q [idx]);
        float2 al = __ldg((const float2*)&g_al[idx]);
        float2 be = __ldg((const float2*)&g_be[idx]);
        *(float2*)&g_v2[idx] = make_float2(v20, v21);
        *(float2*)&g_s [idx] = make_float2(S0, S1);
        // S' = P*S + al + v2*(gamma*v2 - 2*be);  v2' = P*v2 + Q
        float c0 = fmaf(pg.y, v20, -2.0f * be.x);
        float c1 = fmaf(pg.y, v21, -2.0f * be.y);
        S0 = fmaf(pg.x, S0, fmaf(v20, c0, al.x));
        S1 = fmaf(pg.x, S1, fmaf(v21, c1, al.y));
        v20 = fmaf(pg.x, v20, q.x);
        v21 = fmaf(pg.x, v21, q.y);
    }
}

// Pass 2: replay each chunk with exact start state, emit outputs.
__global__ __launch_bounds__(256)
void pass2_kernel(const float* __restrict__ in, float* __restrict__ out) {
    int pr = blockIdx.x * 256 + threadIdx.x;
    int c  = blockIdx.y;
    if (pr >= NPAIRS) return;
    int n  = pr / FC2;
    int fp = pr - n * FC2;
    size_t base = ((size_t)n * T_LEN + (size_t)c * LCH) * FC2 + fp;
    const float2* xp = (const float2*)in  + base;
    float2*       yp = (float2*)out + base;
    const float4* cf = g_c4 + c * LCH;

    int idx = c * NSER + pr * 2;
    float2 v2 = __ldg((const float2*)&g_v2[idx]);
    float2 S  = __ldg((const float2*)&g_s [idx]);
    float v20 = v2.x, v21 = v2.y, S0 = S.x, S1 = S.y;

#pragma unroll
    for (int u = 0; u < LCH; u++) {
        float4 k = __ldg(cf + u);                // (w, a, b, -)
        float2 x = __ldg(xp + (size_t)u * FC2);
        float d0 = x.x - v20;
        float d1 = x.y - v21;
        v20 = fmaf(k.x, d0, v20);
        v21 = fmaf(k.x, d1, v21);
        S0 = fmaf(k.y, S0, (k.z * d0) * d0);
        S1 = fmaf(k.y, S1, (k.z * d1) * d1);
        float r0 = rsqrtf(fmaxf(S0, 0.0f) + 1e-5f);
        float r1 = rsqrtf(fmaxf(S1, 0.0f) + 1e-5f);
        float2 y;
        y.x = (k.y * d0) * r0;
        y.y = (k.y * d1) * r1;
        __stcs(yp + (size_t)u * FC2, y);
    }
}

extern "C" void kernel_launch(void* const* d_in, const int* in_sizes, int n_in,
                              void* d_out, int out_size) {
    const float* s = (const float*)d_in[0];
    float* out = (float*)d_out;
    coef_kernel<<<1, 1024>>>();
    dim3 grid((NPAIRS + 255) / 256, CH);         // (17, 80)
    pass1_kernel<<<grid, 256>>>(s);
    combine_kernel<<<(NPAIRS + 255) / 256, 256>>>();
    pass2_kernel<<<grid, 256>>>(s, out);
}

// round 6
// speedup vs baseline: 1.9624x; 1.9624x over previous
#include <cuda_runtime.h>
#include <math.h>

#define T_LEN  2000
#define FC     514            // 257 * 2
#define NSER   8224           // 16 * 514
#define NPAIRS (NSER / 2)     // 4112 float2 series-pairs
#define FC2    (FC / 2)       // 257 pairs per row
#define CH     40             // number of time chunks
#define LCH    50             // chunk length (CH*LCH == T_LEN)

// Per-t constants: (w, a = 1-w, b = w*a, bP = b * Ppre_u).
__device__ float4 g_c4[T_LEN];
// Per-chunk constants: (P, gamma).
__device__ float2 g_ck[CH];
// Per (chunk, series) scratch.
__device__ float g_q [CH * NSER];
__device__ float g_al[CH * NSER];
__device__ float g_be[CH * NSER];
__device__ float g_v2[CH * NSER];
__device__ float g_s [CH * NSER];

// Integer-exponent power by binary exponentiation: <= 11 iters, ~22 DMULs.
// (Avoids FP64 pow() -- a ~100-op software sequence that poisoned R4/R5.)
__device__ __forceinline__ double dpow(double b, int e) {
    double r = 1.0, p = b;
    while (e) { if (e & 1) r *= p; p *= p; e >>= 1; }
    return r;
}

__global__ void coef_kernel() {
    int t = blockIdx.x * blockDim.x + threadIdx.x;
    if (t >= T_LEN) return;
    const double b  = (double)0.99f;
    const double c1 = (double)(1.0f - 0.99f);   // exact (Sterbenz)
    int u  = t % LCH;
    int t0 = t - u;

    double w  = c1 / (1.0 - dpow(b, t + 1));    // w_0 == 1 exactly
    double a  = 1.0 - w;
    double bb = w * a;
    // Ppre_u = beta^u (1 - beta^t0) / (1 - beta^t);  Ppre_0 = 1.
    double Ppre = (u == 0) ? 1.0
                : dpow(b, u) * (1.0 - dpow(b, t0)) / (1.0 - dpow(b, t));
    g_c4[t] = make_float4((float)w, (float)a, (float)bb, (float)(bb * Ppre));

    if (u == 0) {
        int c = t0 / LCH;
        // P = beta^L (1-beta^t0)/(1-beta^{t0+L}); gamma = (P/beta^t0)(1 - ratio)
        double ratio = (1.0 - dpow(b, t0)) / (1.0 - dpow(b, t0 + LCH));
        double P     = dpow(b, LCH) * ratio;    // 0 for chunk 0 (ratio = 0)
        double ga    = (c == 0) ? 0.0 : (P / dpow(b, t0)) * (1.0 - ratio);
        g_ck[c] = make_float2((float)P, (float)ga);
    }
}

// Pass 1: per (chunk, pair) compute (Q, alpha, beta-hat) from zero start.
__global__ __launch_bounds__(256)
void pass1_kernel(const float* __restrict__ in) {
    int pr = blockIdx.x * 256 + threadIdx.x;
    int c  = blockIdx.y;
    if (pr >= NPAIRS) return;
    int n  = pr / FC2;
    int fp = pr - n * FC2;
    const float2* xp = (const float2*)in
                     + ((size_t)n * T_LEN + (size_t)c * LCH) * FC2 + fp;
    const float4* cf = g_c4 + c * LCH;

    float Q0 = 0.f, Q1 = 0.f, al0 = 0.f, al1 = 0.f, be0 = 0.f, be1 = 0.f;
#pragma unroll 10
    for (int u = 0; u < LCH; u++) {
        float4 k = __ldg(cf + u);                // (w, a, b, bP)
        float2 x = __ldg(xp + (size_t)u * FC2);
        float u0 = x.x - Q0;
        float u1 = x.y - Q1;
        Q0 = fmaf(k.x, u0, Q0);
        Q1 = fmaf(k.x, u1, Q1);
        al0 = fmaf(k.y, al0, (k.z * u0) * u0);
        al1 = fmaf(k.y, al1, (k.z * u1) * u1);
        be0 = fmaf(k.y, be0, k.w * u0);
        be1 = fmaf(k.y, be1, k.w * u1);
    }
    int idx = c * NSER + pr * 2;
    *(float2*)&g_q [idx] = make_float2(Q0, Q1);
    *(float2*)&g_al[idx] = make_float2(al0, al1);
    *(float2*)&g_be[idx] = make_float2(be0, be1);
}

// Combine: serial over the chunks per series-pair.
__global__ __launch_bounds__(256)
void combine_kernel() {
    int pr = blockIdx.x * 256 + threadIdx.x;
    if (pr >= NPAIRS) return;
    float v20 = 0.f, v21 = 0.f, S0 = 0.f, S1 = 0.f;
#pragma unroll 8
    for (int c = 0; c < CH; c++) {
        int idx = c * NSER + pr * 2;
        float2 pg = __ldg(&g_ck[c]);             // (P, gamma)
        float2 q  = __ldg((const float2*)&g_q [idx]);
        float2 al = __ldg((const float2*)&g_al[idx]);
        float2 be = __ldg((const float2*)&g_be[idx]);
        *(float2*)&g_v2[idx] = make_float2(v20, v21);
        *(float2*)&g_s [idx] = make_float2(S0, S1);
        // S' = P*S + al + v2*(gamma*v2 - 2*be);  v2' = P*v2 + Q
        float c0 = fmaf(pg.y, v20, -2.0f * be.x);
        float c1 = fmaf(pg.y, v21, -2.0f * be.y);
        S0 = fmaf(pg.x, S0, fmaf(v20, c0, al.x));
        S1 = fmaf(pg.x, S1, fmaf(v21, c1, al.y));
        v20 = fmaf(pg.x, v20, q.x);
        v21 = fmaf(pg.x, v21, q.y);
    }
}

// Pass 2: replay each chunk with exact start state, emit outputs.
__global__ __launch_bounds__(256)
void pass2_kernel(const float* __restrict__ in, float* __restrict__ out) {
    int pr = blockIdx.x * 256 + threadIdx.x;
    int c  = blockIdx.y;
    if (pr >= NPAIRS) return;
    int n  = pr / FC2;
    int fp = pr - n * FC2;
    size_t base = ((size_t)n * T_LEN + (size_t)c * LCH) * FC2 + fp;
    const float2* xp = (const float2*)in  + base;
    float2*       yp = (float2*)out + base;
    const float4* cf = g_c4 + c * LCH;

    int idx = c * NSER + pr * 2;
    float2 v2 = __ldg((const float2*)&g_v2[idx]);
    float2 S  = __ldg((const float2*)&g_s [idx]);
    float v20 = v2.x, v21 = v2.y, S0 = S.x, S1 = S.y;

#pragma unroll 10
    for (int u = 0; u < LCH; u++) {
        float4 k = __ldg(cf + u);                // (w, a, b, -)
        float2 x = __ldg(xp + (size_t)u * FC2);
        float d0 = x.x - v20;
        float d1 = x.y - v21;
        v20 = fmaf(k.x, d0, v20);
        v21 = fmaf(k.x, d1, v21);
        S0 = fmaf(k.y, S0, (k.z * d0) * d0);
        S1 = fmaf(k.y, S1, (k.z * d1) * d1);
        float r0 = rsqrtf(fmaxf(S0, 0.0f) + 1e-5f);
        float r1 = rsqrtf(fmaxf(S1, 0.0f) + 1e-5f);
        float2 y;
        y.x = (k.y * d0) * r0;
        y.y = (k.y * d1) * r1;
        __stcs(yp + (size_t)u * FC2, y);
    }
}

extern "C" void kernel_launch(void* const* d_in, const int* in_sizes, int n_in,
                              void* d_out, int out_size) {
    const float* s = (const float*)d_in[0];
    float* out = (float*)d_out;
    coef_kernel<<<(T_LEN + 127) / 128, 128>>>();
    dim3 grid((NPAIRS + 255) / 256, CH);         // (17, 40)
    pass1_kernel<<<grid, 256>>>(s);
    combine_kernel<<<(NPAIRS + 255) / 256, 256>>>();
    pass2_kernel<<<grid, 256>>>(s, out);
}